// round 6
// baseline (speedup 1.0000x reference)
#include <cuda_runtime.h>

// Problem constants (fixed by the benchmark)
#define NN     50000
#define KK     10
#define K1     11
#define EMAX   800000
#define NTHR   256
#define RT     64
#define NTILES 782        // ceil(50000/64)
#define CBLK   148        // cold-path persistent blocks (one wave)

// dynamic smem layout (bytes)
#define SMEM_X   0u
#define SMEM_H   16384u
#define SMEM_W1  32768u
#define SMEM_W2  49152u
#define SMEM_RED 65536u
#define DYNSMEM  (65536 + 1024)

typedef unsigned long long ull;

// ---------------- device scratch (static, zero-initialized) ----------------
__device__ float g_wE[EMAX];
__device__ int   g_deg[NN];
__device__ float g_dinv[NN];
__device__ float g_y0[NN * 64];
__device__ float g_y1[NN * 64];
__device__ float g_acc[NN * 64];
__device__ float g_h[NN * 64];
__device__ unsigned g_bar_cnt;
__device__ volatile unsigned g_bar_gen;

__device__ __constant__ float c_binom[K1][K1] = {
    {1,0,0,0,0,0,0,0,0,0,0},
    {1,1,0,0,0,0,0,0,0,0,0},
    {1,2,1,0,0,0,0,0,0,0,0},
    {1,3,3,1,0,0,0,0,0,0,0},
    {1,4,6,4,1,0,0,0,0,0,0},
    {1,5,10,10,5,1,0,0,0,0,0},
    {1,6,15,20,15,6,1,0,0,0,0},
    {1,7,21,35,35,21,7,1,0,0,0},
    {1,8,28,56,70,56,28,8,1,0,0},
    {1,9,36,84,126,126,84,36,9,1,0},
    {1,10,45,120,210,252,210,120,45,10,1}
};

// ---------------------------- PTX helpers -----------------------------------
__device__ __forceinline__ ull ffma2(ull a, ull b, ull c) {
    ull d;
    asm("fma.rn.f32x2 %0, %1, %2, %3;" : "=l"(d) : "l"(a), "l"(b), "l"(c));
    return d;
}
__device__ __forceinline__ ull pack2(float lo, float hi) {
    ull d;
    asm("mov.b64 %0, {%1, %2};" : "=l"(d) : "f"(lo), "f"(hi));
    return d;
}
__device__ __forceinline__ float hsum2(ull v) {
    float a, b;
    asm("mov.b64 {%0, %1}, %2;" : "=f"(a), "=f"(b) : "l"(v));
    return a + b;
}
__device__ __forceinline__ void lds_2x64(ull &a, ull &b, unsigned addr) {
    asm volatile("ld.shared.v2.u64 {%0, %1}, [%2];" : "=l"(a), "=l"(b) : "r"(addr));
}
__device__ __forceinline__ void sts64(unsigned addr, ull v) {
    asm volatile("st.shared.u64 [%0], %1;" :: "r"(addr), "l"(v) : "memory");
}
__device__ __forceinline__ void sts_v4(unsigned addr, float a, float b, float c, float d) {
    asm volatile("st.shared.v4.f32 [%0], {%1, %2, %3, %4};"
                 :: "r"(addr), "f"(a), "f"(b), "f"(c), "f"(d) : "memory");
}
__device__ __forceinline__ void cp16(unsigned dst, const float* src) {
    asm volatile("cp.async.ca.shared.global [%0], [%1], 16;" :: "r"(dst), "l"(src) : "memory");
}

// ---------------------------------------------------------------------------
// Grid barrier over exactly CBLK blocks (cold path only; blocks 0..147 are in
// wave 1 and co-resident; higher blocks exit before any barrier).
// ---------------------------------------------------------------------------
__device__ __forceinline__ void gbar() {
    __syncthreads();
    if (threadIdx.x == 0) {
        unsigned gen = g_bar_gen;
        __threadfence();
        if (atomicAdd(&g_bar_cnt, 1u) == CBLK - 1u) {
            g_bar_cnt = 0u;
            __threadfence();
            g_bar_gen = gen + 1u;
        } else {
            while (g_bar_gen == gen) { }
            __threadfence();
        }
    }
    __syncthreads();
}

// ---------------------------------------------------------------------------
// Gated polynomial propagation: g_acc = sum_m a_m A^m xin (COO atomics).
// ---------------------------------------------------------------------------
__device__ void poly_phase(const float* __restrict__ xin,
                           const int* __restrict__ src,
                           const int* __restrict__ dst,
                           int e, int gt, int gsz, const float* sa) {
    float a0v = sa[0];
    for (int i = gt; i < NN * 64; i += gsz) g_acc[i] = a0v * xin[i];
    const float* yin = xin;
    float* yout = g_y0;
    float* yoth = g_y1;
    for (int m = 1; m <= KK; m++) {
        for (int i = gt; i < NN * 64; i += gsz) yout[i] = 0.0f;
        gbar();
        int tot = e * 32;
        for (int t = gt; t < tot; t += gsz) {
            int ed = t >> 5;
            int l = (t & 31) << 1;
            float w = g_wE[ed];
            int s = src[ed], d = dst[ed];
            float2 v = *(const float2*)(yin + s * 64 + l);
            atomicAdd(&yout[d * 64 + l],     w * v.x);
            atomicAdd(&yout[d * 64 + l + 1], w * v.y);
        }
        gbar();
        float am = sa[m];
        for (int i = gt; i < NN * 64; i += gsz) g_acc[i] += am * yout[i];
        yin = yout;
        float* t2 = yout; yout = yoth; yoth = t2;
    }
    gbar();
}

// ---------------------------------------------------------------------------
// Staging helpers (swizzled layouts)
// X tile: row-major, 256B/row, 16B chunk k4 stored at chunk' = k4 ^ ((row>>2)&7)
// W:      col-major, 256B/col, 16B chunk k4 stored at chunk' = k4 ^ ((col>>2)&7)
//         chunk k4 = k-pairs j=2k4,2k4+1 (covers k = 4k4 .. 4k4+3)
// ---------------------------------------------------------------------------
__device__ __forceinline__ void stage_x(const float* __restrict__ X, int row0,
                                        unsigned sxb, int tid) {
#pragma unroll
    for (int it = 0; it < 4; it++) {
        int q = tid + it * NTHR;
        int row = q >> 4, ch = q & 15;
        int gr = row0 + row;
        if (gr >= NN) gr = NN - 1;
        unsigned d = sxb + row * 256 + ((ch ^ ((row >> 2) & 7)) << 4);
        cp16(d, X + gr * 64 + ch * 4);
    }
}
__device__ __forceinline__ void stage_w(const float* __restrict__ W, float s,
                                        unsigned swb, int tid) {
#pragma unroll
    for (int it = 0; it < 8; it++) {
        int idx = tid + it * NTHR;
        int c = idx >> 5, j = idx & 31;
        int k4 = j >> 1;
        unsigned d = swb + c * 256 + ((k4 ^ ((c >> 2) & 7)) << 4) + (j & 1) * 8;
        sts64(d, pack2(W[(2 * j) * 64 + c] * s, W[(2 * j + 1) * 64 + c] * s));
    }
}

// ---------------------------------------------------------------------------
// 4x4 register-tile GEMM core over one 64x64 tile.
// xrow = sX base + rbase*256 ; rg16 = rg<<4 (X swizzle selector)
// wcol = sW base + cbase*256 ; cs16 = ((cbase>>2)&7)<<4 (W swizzle selector)
// ---------------------------------------------------------------------------
__device__ __forceinline__ void core64(unsigned xrow, unsigned rg16,
                                       unsigned wcol, unsigned cs16,
                                       ull acc[16]) {
#pragma unroll
    for (int i = 0; i < 16; i++) acc[i] = 0ull;
#pragma unroll
    for (int k4 = 0; k4 < 16; k4++) {
        const unsigned xoff = xrow + (((unsigned)(k4 << 4)) ^ rg16);
        const unsigned woff = wcol + (((unsigned)(k4 << 4)) ^ cs16);
        ull x0[4], x1[4], w0[4], w1[4];
#pragma unroll
        for (int r = 0; r < 4; r++) lds_2x64(x0[r], x1[r], xoff + r * 256);
#pragma unroll
        for (int c = 0; c < 4; c++) lds_2x64(w0[c], w1[c], woff + c * 256);
#pragma unroll
        for (int r = 0; r < 4; r++)
#pragma unroll
            for (int c = 0; c < 4; c++) {
                acc[r * 4 + c] = ffma2(x0[r], w0[c], acc[r * 4 + c]);
                acc[r * 4 + c] = ffma2(x1[r], w1[c], acc[r * 4 + c]);
            }
    }
}

// ---------------------------------------------------------------------------
// Kernel. Fast path: one 64-row tile per block, fused GEMM1+GEMM2+fc.
// Cold path (any a_m != 0, m>=1): blocks 0..147 persistent with grid barriers.
// ---------------------------------------------------------------------------
__global__ __launch_bounds__(NTHR, 3) void bernnet(
    const float* __restrict__ x,
    const int*   __restrict__ src,
    const int*   __restrict__ dst,
    int e,
    const float* __restrict__ coe,
    const float* __restrict__ W1, const float* __restrict__ b1,
    const float* __restrict__ W2, const float* __restrict__ b2,
    const float* __restrict__ fcw, const float* __restrict__ fcb,
    float* __restrict__ out)
{
    extern __shared__ __align__(16) char dsm[];
    const unsigned sb = (unsigned)__cvta_generic_to_shared(dsm);
    float* sredf = (float*)(dsm + SMEM_RED);
    __shared__ float s_a[K1];
    __shared__ int   s_need;

    const int tid = threadIdx.x;

    // ---- Bernstein -> monomial coefficients (exact dyadic; per-block) ----
    if (tid < 32) {
        int m = tid;
        float a = 0.0f;
        if (m <= KK) {
            for (int j = 0; j <= KK; j++) {
                float cj = coe[j];
                cj = cj > 0.0f ? cj : 0.0f;
                float B = 0.0f;
                for (int p = 0; p <= j && p <= m; p++) {
                    int q = m - p;
                    if (q > KK - j) continue;
                    float t = c_binom[j][p] * c_binom[KK - j][q];
                    B += (p & 1) ? -t : t;
                }
                a += cj * (c_binom[KK][j] * (1.0f / 1024.0f)) * B;
            }
            s_a[m] = a;
        }
        unsigned msk = __ballot_sync(0xffffffffu, (m >= 1 && m <= KK && a != 0.0f));
        if (m == 0) s_need = msk ? 1 : 0;
    }
    __syncthreads();
    const int need = s_need;

    // thread geometry: warp grid 2(rows) x 4(cols); lane grid 8(rg) x 4(cg)
    const int lane  = tid & 31;
    const int warp  = tid >> 5;
    const int warpR = warp >> 2;        // 0..1
    const int warpC = warp & 3;         // 0..3
    const int rg    = lane >> 2;        // 0..7
    const int cg    = lane & 3;         // 0..3
    const int rbase = warpR * 32 + rg * 4;           // first of 4 rows
    const int cbase = warpC * 16 + cg * 4;           // first of 4 cols
    const unsigned rg16 = (unsigned)(rg << 4);
    const unsigned cs16 = (unsigned)((((cbase >> 2) & 7)) << 4);
    const int hch = (warpC * 4 + cg);   // H store chunk index (= cbase>>2)

    const unsigned xrow = sb + SMEM_X + rbase * 256;
    const unsigned hrow = sb + SMEM_H + rbase * 256;
    const unsigned w1c  = sb + SMEM_W1 + cbase * 256;
    const unsigned w2c  = sb + SMEM_W2 + cbase * 256;

    if (!need) {
        // ================= fast path: p(A) = a0*I ==========================
        const float a0  = s_a[0];
        const int row0  = blockIdx.x * RT;

        stage_x(x, row0, sb + SMEM_X, tid);
        asm volatile("cp.async.commit_group;" ::: "memory");
        stage_w(W1, a0, sb + SMEM_W1, tid);
        stage_w(W2, a0, sb + SMEM_W2, tid);
        const float4 b1v = ((const float4*)b1)[hch];
        const float4 b2v = ((const float4*)b2)[hch];
        const float4 fwv = ((const float4*)fcw)[hch];
        const float  fb  = fcb[0];
        asm volatile("cp.async.wait_group 0;" ::: "memory");
        __syncthreads();

        ull acc[16];
        // ---- GEMM1 -> sH (relu) ----
        core64(xrow, rg16, w1c, cs16, acc);
#pragma unroll
        for (int r = 0; r < 4; r++) {
            float h0 = fmaxf(hsum2(acc[r * 4 + 0]) + b1v.x, 0.0f);
            float h1 = fmaxf(hsum2(acc[r * 4 + 1]) + b1v.y, 0.0f);
            float h2 = fmaxf(hsum2(acc[r * 4 + 2]) + b1v.z, 0.0f);
            float h3 = fmaxf(hsum2(acc[r * 4 + 3]) + b1v.w, 0.0f);
            sts_v4(hrow + r * 256 + (((unsigned)hch ^ (unsigned)rg) << 4),
                   h0, h1, h2, h3);
        }
        __syncthreads();

        // ---- GEMM2 + fc ----
        core64(hrow, rg16, w2c, cs16, acc);
        float p[4];
#pragma unroll
        for (int r = 0; r < 4; r++) {
            p[r] = fmaxf(hsum2(acc[r * 4 + 0]) + b2v.x, 0.0f) * fwv.x
                 + fmaxf(hsum2(acc[r * 4 + 1]) + b2v.y, 0.0f) * fwv.y
                 + fmaxf(hsum2(acc[r * 4 + 2]) + b2v.z, 0.0f) * fwv.z
                 + fmaxf(hsum2(acc[r * 4 + 3]) + b2v.w, 0.0f) * fwv.w;
        }
#pragma unroll
        for (int r = 0; r < 4; r++) {
            p[r] += __shfl_xor_sync(0xffffffffu, p[r], 1);
            p[r] += __shfl_xor_sync(0xffffffffu, p[r], 2);
        }
        if (cg == 0) {
#pragma unroll
            for (int r = 0; r < 4; r++)
                sredf[(rbase + r) * 4 + warpC] = p[r];
        }
        __syncthreads();
        if (tid < RT) {
            float4 v = ((const float4*)sredf)[tid];
            int g = row0 + tid;
            if (g < NN) out[g] = v.x + v.y + v.z + v.w + fb;
        }
        return;
    }

    // ================= cold path: full polynomial semantics =================
    if (blockIdx.x >= CBLK) return;
    const int gt  = blockIdx.x * NTHR + tid;
    const int gsz = CBLK * NTHR;

    for (int i = gt; i < NN; i += gsz) g_deg[i] = 0;
    gbar();
    for (int t = gt; t < e; t += gsz) atomicAdd(&g_deg[src[t]], 1);
    gbar();
    for (int i = gt; i < NN; i += gsz) {
        int d = g_deg[i];
        g_dinv[i] = d > 0 ? rsqrtf((float)d) : 0.0f;
    }
    gbar();
    for (int t = gt; t < e; t += gsz) g_wE[t] = g_dinv[src[t]] * g_dinv[dst[t]];
    gbar();

    poly_phase(x, src, dst, e, gt, gsz, s_a);

    // GEMM1 pass: g_h = relu(g_acc @ W1 + b1)
    {
        stage_w(W1, 1.0f, sb + SMEM_W1, tid);
        const float4 b1v = ((const float4*)b1)[hch];
        for (int t = blockIdx.x; t < NTILES; t += CBLK) {
            __syncthreads();
            stage_x(g_acc, t * RT, sb + SMEM_X, tid);
            asm volatile("cp.async.commit_group;\n\tcp.async.wait_group 0;" ::: "memory");
            __syncthreads();
            ull acc[16];
            core64(xrow, rg16, w1c, cs16, acc);
#pragma unroll
            for (int r = 0; r < 4; r++) {
                int g = t * RT + rbase + r;
                if (g < NN) {
                    float4 hv;
                    hv.x = fmaxf(hsum2(acc[r * 4 + 0]) + b1v.x, 0.0f);
                    hv.y = fmaxf(hsum2(acc[r * 4 + 1]) + b1v.y, 0.0f);
                    hv.z = fmaxf(hsum2(acc[r * 4 + 2]) + b1v.z, 0.0f);
                    hv.w = fmaxf(hsum2(acc[r * 4 + 3]) + b1v.w, 0.0f);
                    *(float4*)(g_h + g * 64 + cbase) = hv;
                }
            }
        }
    }
    gbar();

    poly_phase(g_h, src, dst, e, gt, gsz, s_a);

    // GEMM2 + fc pass
    {
        stage_w(W2, 1.0f, sb + SMEM_W2, tid);
        const float4 b2v = ((const float4*)b2)[hch];
        const float4 fwv = ((const float4*)fcw)[hch];
        const float  fb  = fcb[0];
        for (int t = blockIdx.x; t < NTILES; t += CBLK) {
            __syncthreads();
            stage_x(g_acc, t * RT, sb + SMEM_X, tid);
            asm volatile("cp.async.commit_group;\n\tcp.async.wait_group 0;" ::: "memory");
            __syncthreads();
            ull acc[16];
            core64(xrow, rg16, w2c, cs16, acc);
            float p[4];
#pragma unroll
            for (int r = 0; r < 4; r++) {
                p[r] = fmaxf(hsum2(acc[r * 4 + 0]) + b2v.x, 0.0f) * fwv.x
                     + fmaxf(hsum2(acc[r * 4 + 1]) + b2v.y, 0.0f) * fwv.y
                     + fmaxf(hsum2(acc[r * 4 + 2]) + b2v.z, 0.0f) * fwv.z
                     + fmaxf(hsum2(acc[r * 4 + 3]) + b2v.w, 0.0f) * fwv.w;
                p[r] += __shfl_xor_sync(0xffffffffu, p[r], 1);
                p[r] += __shfl_xor_sync(0xffffffffu, p[r], 2);
            }
            if (cg == 0)
#pragma unroll
                for (int r = 0; r < 4; r++)
                    sredf[(rbase + r) * 4 + warpC] = p[r];
            __syncthreads();
            if (tid < RT) {
                float4 v = ((const float4*)sredf)[tid];
                int g = t * RT + tid;
                if (g < NN) out[g] = v.x + v.y + v.z + v.w + fb;
            }
        }
    }
}

// ---------------------------------------------------------------------------
extern "C" void kernel_launch(void* const* d_in, const int* in_sizes, int n_in,
                              void* d_out, int out_size) {
    const float* x   = (const float*)d_in[0];
    const int*   ei  = (const int*)d_in[1];
    const float* coe = (const float*)d_in[2];
    const float* W1  = (const float*)d_in[3];
    const float* b1  = (const float*)d_in[4];
    const float* W2  = (const float*)d_in[5];
    const float* b2  = (const float*)d_in[6];
    const float* fcw = (const float*)d_in[7];
    const float* fcb = (const float*)d_in[8];
    float* out = (float*)d_out;

    int e = in_sizes[1] / 2;
    const int* src = ei;
    const int* dst = ei + e;

    static int smem_set = 0;
    if (!smem_set) {
        cudaFuncSetAttribute(bernnet, cudaFuncAttributeMaxDynamicSharedMemorySize,
                             DYNSMEM);
        smem_set = 1;
    }

    bernnet<<<NTILES, NTHR, DYNSMEM>>>(x, src, dst, e, coe,
                                       W1, b1, W2, b2, fcw, fcb, out);
}